// round 1
// baseline (speedup 1.0000x reference)
#include <cuda_runtime.h>
#include <math.h>

// Problem constants
#define BSZ 4
#define TLEN 2048
#define CDIM 1024
#define NH 16
#define HD 64
#define MTOT (BSZ * TLEN)        // 8192
#define N_QKV (3 * CDIM)         // 3072
#define ATT_SCALE 0.125f         // 1/sqrt(64)

// Scratch (allocation-free rule: __device__ globals)
__device__ float g_q[(size_t)BSZ * NH * TLEN * HD];   // [bh][t][d]
__device__ float g_k[(size_t)BSZ * NH * TLEN * HD];
__device__ float g_v[(size_t)BSZ * NH * TLEN * HD];
__device__ float g_att[(size_t)MTOT * CDIM];          // [b,t,c]

// ---------------------------------------------------------------------------
// GEMM 1: qkv = x @ w_qkv^T, scattered into g_q/g_k/g_v with [bh][t][d] layout
// A: x [8192, 1024] row-major; B: w_qkv [3072, 1024] row-major (K-major both)
// 128x128x16 tile, 256 threads, 8x8 per-thread fragment.
// ---------------------------------------------------------------------------
#define GBK 16
#define GLD 132   // padded stride for k-major smem tiles

__global__ __launch_bounds__(256) void qkv_gemm(const float* __restrict__ A,
                                                const float* __restrict__ Bw) {
    __shared__ float As[GBK * GLD];
    __shared__ float Bs[GBK * GLD];
    const int tid = threadIdx.x;
    const int tx = tid & 15, ty = tid >> 4;
    const int bm = blockIdx.y, bn = blockIdx.x;
    const float* Ag = A + (size_t)bm * 128 * CDIM;
    const float* Bg = Bw + (size_t)bn * 128 * CDIM;

    float acc[8][8];
#pragma unroll
    for (int i = 0; i < 8; i++)
#pragma unroll
        for (int j = 0; j < 8; j++) acc[i][j] = 0.f;

    for (int kt = 0; kt < CDIM; kt += GBK) {
#pragma unroll
        for (int l = 0; l < 2; l++) {
            int idx = tid + l * 256;
            int row = idx >> 2;
            int c4 = (idx & 3) * 4;
            float4 av = *(const float4*)(Ag + (size_t)row * CDIM + kt + c4);
            As[(c4 + 0) * GLD + row] = av.x;
            As[(c4 + 1) * GLD + row] = av.y;
            As[(c4 + 2) * GLD + row] = av.z;
            As[(c4 + 3) * GLD + row] = av.w;
            float4 bv = *(const float4*)(Bg + (size_t)row * CDIM + kt + c4);
            Bs[(c4 + 0) * GLD + row] = bv.x;
            Bs[(c4 + 1) * GLD + row] = bv.y;
            Bs[(c4 + 2) * GLD + row] = bv.z;
            Bs[(c4 + 3) * GLD + row] = bv.w;
        }
        __syncthreads();
#pragma unroll
        for (int k = 0; k < GBK; k++) {
            float4 a0 = *(float4*)&As[k * GLD + ty * 8];
            float4 a1 = *(float4*)&As[k * GLD + ty * 8 + 4];
            float4 b0 = *(float4*)&Bs[k * GLD + tx * 4];
            float4 b1 = *(float4*)&Bs[k * GLD + 64 + tx * 4];
            float a[8] = {a0.x, a0.y, a0.z, a0.w, a1.x, a1.y, a1.z, a1.w};
            float b[8] = {b0.x, b0.y, b0.z, b0.w, b1.x, b1.y, b1.z, b1.w};
#pragma unroll
            for (int i = 0; i < 8; i++)
#pragma unroll
                for (int j = 0; j < 8; j++) acc[i][j] += a[i] * b[j];
        }
        __syncthreads();
    }

    // Epilogue: scatter into q/k/v [bh][t][d]
    const int m0 = bm * 128 + ty * 8;
#pragma unroll
    for (int i = 0; i < 8; i++) {
        int m = m0 + i;
        int bb = m >> 11;        // /2048
        int t = m & (TLEN - 1);
#pragma unroll
        for (int q2 = 0; q2 < 2; q2++) {
            int ncol = bn * 128 + q2 * 64 + tx * 4;
            int which = ncol >> 10;
            int o = ncol & 1023;
            int h = o >> 6;
            int d = o & 63;
            float* dst = (which == 0) ? g_q : (which == 1) ? g_k : g_v;
            float4 v;
            v.x = acc[i][q2 * 4 + 0];
            v.y = acc[i][q2 * 4 + 1];
            v.z = acc[i][q2 * 4 + 2];
            v.w = acc[i][q2 * 4 + 3];
            *(float4*)(dst + ((size_t)(bb * NH + h) * TLEN + t) * HD + d) = v;
        }
    }
}

// ---------------------------------------------------------------------------
// Flash attention (causal), fp32 SIMT.
// Block: one (b,h, 64-query tile). 256 threads as 16x16 grid, 4x4 fragments.
// ---------------------------------------------------------------------------
#define ALD2 68   // padded stride for d-major Q/K and k-major P tiles

__global__ __launch_bounds__(256) void attn_kernel() {
    extern __shared__ float sm[];
    float* Qs = sm;                    // [d][q] stride ALD2, pre-scaled
    float* Ks = Qs + 64 * ALD2;        // [d][k] stride ALD2
    float* Ps = Ks + 64 * ALD2;        // [k][q] stride ALD2
    float* Vs = Ps + 64 * ALD2;        // [k][d] stride 64

    const int qt = blockIdx.x;         // 0..31
    const int bh = blockIdx.y;         // 0..63
    const int tid = threadIdx.x;
    const int tx = tid & 15, ty = tid >> 4;

    const float* qb = g_q + ((size_t)bh * TLEN + qt * 64) * HD;
    const float* kb = g_k + (size_t)bh * TLEN * HD;
    const float* vb = g_v + (size_t)bh * TLEN * HD;

    // Load Q tile transposed (d-major), scale folded in
#pragma unroll
    for (int r0 = 0; r0 < 64; r0 += 16) {
        int row = r0 + ty;
        int c4 = tx * 4;
        float4 v4 = *(const float4*)(qb + row * HD + c4);
        Qs[(c4 + 0) * ALD2 + row] = v4.x * ATT_SCALE;
        Qs[(c4 + 1) * ALD2 + row] = v4.y * ATT_SCALE;
        Qs[(c4 + 2) * ALD2 + row] = v4.z * ATT_SCALE;
        Qs[(c4 + 3) * ALD2 + row] = v4.w * ATT_SCALE;
    }

    float o[16];
    float mrow[4], lrow[4];
#pragma unroll
    for (int i = 0; i < 16; i++) o[i] = 0.f;
#pragma unroll
    for (int i = 0; i < 4; i++) { mrow[i] = -1e30f; lrow[i] = 0.f; }

    for (int kt2 = 0; kt2 <= qt; kt2++) {
        __syncthreads();  // guard K/V/P reuse (also covers initial Q stores)
        const float* kb2 = kb + kt2 * 64 * HD;
        const float* vb2 = vb + kt2 * 64 * HD;
#pragma unroll
        for (int r0 = 0; r0 < 64; r0 += 16) {
            int row = r0 + ty;
            int c4 = tx * 4;
            float4 kv4 = *(const float4*)(kb2 + row * HD + c4);
            Ks[(c4 + 0) * ALD2 + row] = kv4.x;
            Ks[(c4 + 1) * ALD2 + row] = kv4.y;
            Ks[(c4 + 2) * ALD2 + row] = kv4.z;
            Ks[(c4 + 3) * ALD2 + row] = kv4.w;
            float4 vv4 = *(const float4*)(vb2 + row * HD + c4);
            *(float4*)&Vs[row * 64 + c4] = vv4;
        }
        __syncthreads();

        // S = Q K^T fragment (4 q-rows x 4 k-cols)
        float s[16];
#pragma unroll
        for (int i = 0; i < 16; i++) s[i] = 0.f;
#pragma unroll
        for (int j = 0; j < 64; j++) {
            float4 a4 = *(float4*)&Qs[j * ALD2 + ty * 4];
            float4 b4 = *(float4*)&Ks[j * ALD2 + tx * 4];
            float a[4] = {a4.x, a4.y, a4.z, a4.w};
            float b[4] = {b4.x, b4.y, b4.z, b4.w};
#pragma unroll
            for (int i = 0; i < 4; i++)
#pragma unroll
                for (int jj = 0; jj < 4; jj++) s[i * 4 + jj] += a[i] * b[jj];
        }

        // Causal mask (only diagonal tile mixes valid/invalid)
        if (kt2 == qt) {
#pragma unroll
            for (int i = 0; i < 4; i++)
#pragma unroll
                for (int jj = 0; jj < 4; jj++)
                    if (tx * 4 + jj > ty * 4 + i) s[i * 4 + jj] = -1e30f;
        }

        // Online softmax update per q-row
#pragma unroll
        for (int i = 0; i < 4; i++) {
            float tm = s[i * 4];
            tm = fmaxf(tm, s[i * 4 + 1]);
            tm = fmaxf(tm, s[i * 4 + 2]);
            tm = fmaxf(tm, s[i * 4 + 3]);
#pragma unroll
            for (int off = 8; off >= 1; off >>= 1)
                tm = fmaxf(tm, __shfl_xor_sync(0xffffffffu, tm, off));
            float mn = fmaxf(mrow[i], tm);
            float alpha = __expf(mrow[i] - mn);
            mrow[i] = mn;
            float rs = 0.f;
#pragma unroll
            for (int jj = 0; jj < 4; jj++) {
                float p = __expf(s[i * 4 + jj] - mn);
                s[i * 4 + jj] = p;
                rs += p;
            }
#pragma unroll
            for (int off = 8; off >= 1; off >>= 1)
                rs += __shfl_xor_sync(0xffffffffu, rs, off);
            lrow[i] = lrow[i] * alpha + rs;
#pragma unroll
            for (int jj = 0; jj < 4; jj++) o[i * 4 + jj] *= alpha;
            // P transposed into smem: Ps[k][q]
#pragma unroll
            for (int jj = 0; jj < 4; jj++)
                Ps[(tx * 4 + jj) * ALD2 + ty * 4 + i] = s[i * 4 + jj];
        }
        __syncthreads();

        // O += P V  (thread frag: 4 q-rows x 4 d-cols)
#pragma unroll
        for (int j = 0; j < 64; j++) {
            float4 a4 = *(float4*)&Ps[j * ALD2 + ty * 4];
            float4 b4 = *(float4*)&Vs[j * 64 + tx * 4];
            float a[4] = {a4.x, a4.y, a4.z, a4.w};
            float b[4] = {b4.x, b4.y, b4.z, b4.w};
#pragma unroll
            for (int i = 0; i < 4; i++)
#pragma unroll
                for (int jj = 0; jj < 4; jj++) o[i * 4 + jj] += a[i] * b[jj];
        }
    }

    // Normalize + write to g_att [b, t, h*64 + d]
    const int b = bh >> 4, h = bh & 15;
#pragma unroll
    for (int i = 0; i < 4; i++) {
        float inv = 1.f / lrow[i];
        int trow = qt * 64 + ty * 4 + i;
        float4 ov;
        ov.x = o[i * 4 + 0] * inv;
        ov.y = o[i * 4 + 1] * inv;
        ov.z = o[i * 4 + 2] * inv;
        ov.w = o[i * 4 + 3] * inv;
        *(float4*)(g_att + ((size_t)b * TLEN + trow) * CDIM + h * 64 + tx * 4) = ov;
    }
}

// ---------------------------------------------------------------------------
// GEMM 2: out = g_att @ w_out^T + b_out
// ---------------------------------------------------------------------------
__global__ __launch_bounds__(256) void out_gemm(const float* __restrict__ Bw,
                                                const float* __restrict__ bias,
                                                float* __restrict__ out) {
    __shared__ float As[GBK * GLD];
    __shared__ float Bs[GBK * GLD];
    const int tid = threadIdx.x;
    const int tx = tid & 15, ty = tid >> 4;
    const int bm = blockIdx.y, bn = blockIdx.x;
    const float* Ag = g_att + (size_t)bm * 128 * CDIM;
    const float* Bg = Bw + (size_t)bn * 128 * CDIM;

    float acc[8][8];
#pragma unroll
    for (int i = 0; i < 8; i++)
#pragma unroll
        for (int j = 0; j < 8; j++) acc[i][j] = 0.f;

    for (int kt = 0; kt < CDIM; kt += GBK) {
#pragma unroll
        for (int l = 0; l < 2; l++) {
            int idx = tid + l * 256;
            int row = idx >> 2;
            int c4 = (idx & 3) * 4;
            float4 av = *(const float4*)(Ag + (size_t)row * CDIM + kt + c4);
            As[(c4 + 0) * GLD + row] = av.x;
            As[(c4 + 1) * GLD + row] = av.y;
            As[(c4 + 2) * GLD + row] = av.z;
            As[(c4 + 3) * GLD + row] = av.w;
            float4 bv = *(const float4*)(Bg + (size_t)row * CDIM + kt + c4);
            Bs[(c4 + 0) * GLD + row] = bv.x;
            Bs[(c4 + 1) * GLD + row] = bv.y;
            Bs[(c4 + 2) * GLD + row] = bv.z;
            Bs[(c4 + 3) * GLD + row] = bv.w;
        }
        __syncthreads();
#pragma unroll
        for (int k = 0; k < GBK; k++) {
            float4 a0 = *(float4*)&As[k * GLD + ty * 8];
            float4 a1 = *(float4*)&As[k * GLD + ty * 8 + 4];
            float4 b0 = *(float4*)&Bs[k * GLD + tx * 4];
            float4 b1 = *(float4*)&Bs[k * GLD + 64 + tx * 4];
            float a[8] = {a0.x, a0.y, a0.z, a0.w, a1.x, a1.y, a1.z, a1.w};
            float b[8] = {b0.x, b0.y, b0.z, b0.w, b1.x, b1.y, b1.z, b1.w};
#pragma unroll
            for (int i = 0; i < 8; i++)
#pragma unroll
                for (int j = 0; j < 8; j++) acc[i][j] += a[i] * b[j];
        }
        __syncthreads();
    }

    const int m0 = bm * 128 + ty * 8;
#pragma unroll
    for (int i = 0; i < 8; i++) {
        int m = m0 + i;
#pragma unroll
        for (int q2 = 0; q2 < 2; q2++) {
            int ncol = bn * 128 + q2 * 64 + tx * 4;
            float4 bv = *(const float4*)(bias + ncol);
            float4 v;
            v.x = acc[i][q2 * 4 + 0] + bv.x;
            v.y = acc[i][q2 * 4 + 1] + bv.y;
            v.z = acc[i][q2 * 4 + 2] + bv.z;
            v.w = acc[i][q2 * 4 + 3] + bv.w;
            *(float4*)(out + (size_t)m * CDIM + ncol) = v;
        }
    }
}

// ---------------------------------------------------------------------------
extern "C" void kernel_launch(void* const* d_in, const int* in_sizes, int n_in,
                              void* d_out, int out_size) {
    const float* x = (const float*)d_in[0];
    const float* w_qkv = (const float*)d_in[1];
    const float* w_out = (const float*)d_in[2];
    const float* b_out = (const float*)d_in[3];
    float* out = (float*)d_out;

    // 1) QKV projection
    qkv_gemm<<<dim3(N_QKV / 128, MTOT / 128), 256>>>(x, w_qkv);

    // 2) Flash attention
    size_t shm = (size_t)(3 * 64 * ALD2 + 64 * 64) * sizeof(float);
    cudaFuncSetAttribute(attn_kernel, cudaFuncAttributeMaxDynamicSharedMemorySize,
                         (int)shm);
    attn_kernel<<<dim3(TLEN / 64, BSZ * NH), 256, shm>>>();

    // 3) Output projection + bias
    out_gemm<<<dim3(CDIM / 128, MTOT / 128), 256>>>(w_out, b_out, out);
}

// round 6
// speedup vs baseline: 1.5098x; 1.5098x over previous
#include <cuda_runtime.h>
#include <cuda_bf16.h>
#include <cstdint>

// Problem constants
#define BSZ 4
#define TLEN 2048
#define CDIM 1024
#define NH 16
#define HD 64
#define MTOT (BSZ * TLEN)        // 8192
#define N_QKV (3 * CDIM)         // 3072
#define KDIM 1024
#define ATT_SCALE 0.125f

// ---------------------------------------------------------------------------
// Scratch (__device__ globals; referenced ONLY inside device code)
// ---------------------------------------------------------------------------
__device__ float g_q[(size_t)BSZ * NH * TLEN * HD];
__device__ float g_k[(size_t)BSZ * NH * TLEN * HD];
__device__ float g_v[(size_t)BSZ * NH * TLEN * HD];
__device__ float g_att[(size_t)MTOT * CDIM];

// ---------------------------------------------------------------------------
// Helpers (arch-agnostic PTX: mma.sync / ldmatrix only)
// ---------------------------------------------------------------------------
__device__ __forceinline__ uint32_t smem_u32(const void* p) {
    uint32_t a;
    asm("{ .reg .u64 t; cvta.to.shared.u64 t, %1; cvt.u32.u64 %0, t; }"
        : "=r"(a) : "l"(p));
    return a;
}

__device__ __forceinline__ void mma16816(float c[4], uint32_t a0, uint32_t a1,
                                         uint32_t a2, uint32_t a3,
                                         uint32_t b0, uint32_t b1) {
    asm volatile(
        "mma.sync.aligned.m16n8k16.row.col.f32.bf16.bf16.f32 "
        "{%0,%1,%2,%3}, {%4,%5,%6,%7}, {%8,%9}, {%0,%1,%2,%3};"
        : "+f"(c[0]), "+f"(c[1]), "+f"(c[2]), "+f"(c[3])
        : "r"(a0), "r"(a1), "r"(a2), "r"(a3), "r"(b0), "r"(b1));
}

__device__ __forceinline__ void ldm_x4(uint32_t r[4], uint32_t addr) {
    asm volatile("ldmatrix.sync.aligned.m8n8.x4.shared.b16 {%0,%1,%2,%3}, [%4];"
                 : "=r"(r[0]), "=r"(r[1]), "=r"(r[2]), "=r"(r[3]) : "r"(addr));
}

// pack two floats -> bf16x2 (lo_val in low half, hi_val in high half), RN
__device__ __forceinline__ uint32_t cvt2bf(float lo_val, float hi_val) {
    uint32_t r;
    asm("cvt.rn.bf16x2.f32 %0, %1, %2;" : "=r"(r) : "f"(hi_val), "f"(lo_val));
    return r;
}

// ---------------------------------------------------------------------------
// mma.sync bf16x3 GEMM with in-kernel fp32->hi/lo split.
// C[M,N] = A[M,K] @ B[N,K]^T, fp32 inputs (both K-major).
// BM=BN=128, BK=32, single-stage STATIC 40KB smem, 256 threads, 8 warps.
// epi=0: A = A_arg (x), scatter fp32 Q/K/V.
// epi=1: A = g_att (device-side symbol!), out = C + bias.
// ---------------------------------------------------------------------------
#define GBK 32
#define ALDS 40                       // smem row stride (bf16 elems)
#define TILE_ELE (128 * ALDS)         // 5120 elems

__global__ __launch_bounds__(256) void mm_kernel(
    const float* __restrict__ A_arg, const float* __restrict__ B,
    const float* __restrict__ bias, float* __restrict__ out, int epi) {
    __shared__ __align__(16) uint16_t smbuf[4 * TILE_ELE];  // Ah, Al, Bh, Bl
    const int tid = threadIdx.x;
    const int lane = tid & 31, w = tid >> 5;
    const int wm = w & 3, wn = w >> 2;
    const int bm = blockIdx.y, bn = blockIdx.x;

    // CRITICAL: device globals must be resolved in device code, never passed
    // as kernel args from host (host shadow symbol -> ATS-readable zeros).
    const float* A = (epi == 0) ? A_arg : g_att;

    const float* Ag = A + (size_t)bm * 128 * KDIM;
    const float* Bg = B + (size_t)bn * 128 * KDIM;

    float c[2][8][4];
#pragma unroll
    for (int i = 0; i < 2; i++)
#pragma unroll
        for (int j = 0; j < 8; j++)
#pragma unroll
            for (int k = 0; k < 4; k++) c[i][j][k] = 0.f;

    const uint32_t smb = smem_u32(smbuf);
    const uint32_t sAh = smb;                       // bytes
    const uint32_t sAl = smb + 2 * TILE_ELE;
    const uint32_t sBh = smb + 2 * (2 * TILE_ELE);
    const uint32_t sBl = smb + 2 * (3 * TILE_ELE);

    const int NIT = KDIM / GBK;        // 32
    for (int it = 0; it < NIT; it++) {
        const int kt = it * GBK;
        // Load fp32 tiles, split hi/lo in-register, store bf16 tiles.
        // 2048 float4-chunks per iter (A:1024, B:1024), 8 per thread.
#pragma unroll
        for (int j = 0; j < 8; j++) {
            int q = tid + j * 256;
            int tb = q >> 10;                 // 0:A 1:B
            int r = (q >> 3) & 127;
            int c4 = (q & 7) * 4;
            const float* src = (tb ? Bg : Ag) + (size_t)r * KDIM + kt + c4;
            float4 v = *(const float4*)src;
            // hi = truncate mantissa to bf16 (exact); lo = rn(v - hi)
            uint32_t bx = __float_as_uint(v.x), by = __float_as_uint(v.y);
            uint32_t bz = __float_as_uint(v.z), bw = __float_as_uint(v.w);
            uint32_t h01 = __byte_perm(bx, by, 0x7632);  // {bx.hi16, by.hi16}
            uint32_t h23 = __byte_perm(bz, bw, 0x7632);
            float lx = v.x - __uint_as_float(bx & 0xFFFF0000u);
            float ly = v.y - __uint_as_float(by & 0xFFFF0000u);
            float lz = v.z - __uint_as_float(bz & 0xFFFF0000u);
            float lw = v.w - __uint_as_float(bw & 0xFFFF0000u);
            uint32_t l01 = cvt2bf(lx, ly);
            uint32_t l23 = cvt2bf(lz, lw);
            uint32_t off = 2 * (r * ALDS + c4);          // bytes within tile
            uint32_t hbase = (tb ? sBh : sAh) + off;
            uint32_t lbase = (tb ? sBl : sAl) + off;
            uint2 hv; hv.x = h01; hv.y = h23;
            uint2 lv; lv.x = l01; lv.y = l23;
            *(uint2*)(smbuf + ((hbase - smb) >> 1)) = hv;
            *(uint2*)(smbuf + ((lbase - smb) >> 1)) = lv;
        }
        __syncthreads();

#pragma unroll
        for (int ks = 0; ks < 2; ks++) {
            uint32_t ah[2][4], al[2][4];
#pragma unroll
            for (int mi = 0; mi < 2; mi++) {
                uint32_t off = 2 * ((wm * 32 + 16 * mi + (lane & 15)) * ALDS +
                                    ks * 16 + (lane >> 4) * 8);
                ldm_x4(ah[mi], sAh + off);
                ldm_x4(al[mi], sAl + off);
            }
#pragma unroll
            for (int njp = 0; njp < 4; njp++) {
                int rowB = wn * 64 + njp * 16 + (lane & 7) + ((lane >> 4) & 1) * 8;
                uint32_t off = 2 * (rowB * ALDS + ks * 16 + ((lane >> 3) & 1) * 8);
                uint32_t bh4[4], bl4[4];
                ldm_x4(bh4, sBh + off);
                ldm_x4(bl4, sBl + off);
#pragma unroll
                for (int mi = 0; mi < 2; mi++) {
                    mma16816(c[mi][2 * njp], ah[mi][0], ah[mi][1], ah[mi][2], ah[mi][3], bh4[0], bh4[1]);
                    mma16816(c[mi][2 * njp], ah[mi][0], ah[mi][1], ah[mi][2], ah[mi][3], bl4[0], bl4[1]);
                    mma16816(c[mi][2 * njp], al[mi][0], al[mi][1], al[mi][2], al[mi][3], bh4[0], bh4[1]);
                    mma16816(c[mi][2 * njp + 1], ah[mi][0], ah[mi][1], ah[mi][2], ah[mi][3], bh4[2], bh4[3]);
                    mma16816(c[mi][2 * njp + 1], ah[mi][0], ah[mi][1], ah[mi][2], ah[mi][3], bl4[2], bl4[3]);
                    mma16816(c[mi][2 * njp + 1], al[mi][0], al[mi][1], al[mi][2], al[mi][3], bh4[2], bh4[3]);
                }
            }
        }
        __syncthreads();
    }

    // Epilogue
    const int rin = lane >> 2, col2 = (lane & 3) * 2;
#pragma unroll
    for (int mi = 0; mi < 2; mi++) {
#pragma unroll
        for (int h2 = 0; h2 < 2; h2++) {
            int m = bm * 128 + wm * 32 + mi * 16 + rin + h2 * 8;
#pragma unroll
            for (int nj = 0; nj < 8; nj++) {
                int n = bn * 128 + wn * 64 + nj * 8 + col2;
                float v0 = c[mi][nj][h2 * 2 + 0];
                float v1 = c[mi][nj][h2 * 2 + 1];
                if (epi == 0) {
                    int which = n >> 10;
                    int o = n & 1023;
                    int h = o >> 6, d = o & 63;
                    float* dst = (which == 0) ? g_q : (which == 1) ? g_k : g_v;
                    int bb = m >> 11, t = m & (TLEN - 1);
                    float2 o2; o2.x = v0; o2.y = v1;
                    *(float2*)(dst + ((size_t)(bb * NH + h) * TLEN + t) * HD + d) = o2;
                } else {
                    float2 o2;
                    o2.x = v0 + bias[n];
                    o2.y = v1 + bias[n + 1];
                    *(float2*)(out + (size_t)m * CDIM + n) = o2;
                }
            }
        }
    }
}

// ---------------------------------------------------------------------------
// Flash attention (causal), fp32 SIMT — PROVEN in R1 (rel_err 1.2e-6), verbatim.
// ---------------------------------------------------------------------------
#define ALD2 68

__global__ __launch_bounds__(256) void attn_kernel() {
    extern __shared__ float smf[];
    float* Qs = smf;
    float* Ks = Qs + 64 * ALD2;
    float* Ps = Ks + 64 * ALD2;
    float* Vs = Ps + 64 * ALD2;

    const int qt = blockIdx.x;
    const int bh = blockIdx.y;
    const int tid = threadIdx.x;
    const int tx = tid & 15, ty = tid >> 4;

    const float* qb = g_q + ((size_t)bh * TLEN + qt * 64) * HD;
    const float* kb = g_k + (size_t)bh * TLEN * HD;
    const float* vb = g_v + (size_t)bh * TLEN * HD;

#pragma unroll
    for (int r0 = 0; r0 < 64; r0 += 16) {
        int row = r0 + ty;
        int c4 = tx * 4;
        float4 v4 = *(const float4*)(qb + row * HD + c4);
        Qs[(c4 + 0) * ALD2 + row] = v4.x * ATT_SCALE;
        Qs[(c4 + 1) * ALD2 + row] = v4.y * ATT_SCALE;
        Qs[(c4 + 2) * ALD2 + row] = v4.z * ATT_SCALE;
        Qs[(c4 + 3) * ALD2 + row] = v4.w * ATT_SCALE;
    }

    float o[16];
    float mrow[4], lrow[4];
#pragma unroll
    for (int i = 0; i < 16; i++) o[i] = 0.f;
#pragma unroll
    for (int i = 0; i < 4; i++) { mrow[i] = -1e30f; lrow[i] = 0.f; }

    for (int kt2 = 0; kt2 <= qt; kt2++) {
        __syncthreads();
        const float* kb2 = kb + kt2 * 64 * HD;
        const float* vb2 = vb + kt2 * 64 * HD;
#pragma unroll
        for (int r0 = 0; r0 < 64; r0 += 16) {
            int row = r0 + ty;
            int c4 = tx * 4;
            float4 kv4 = *(const float4*)(kb2 + row * HD + c4);
            Ks[(c4 + 0) * ALD2 + row] = kv4.x;
            Ks[(c4 + 1) * ALD2 + row] = kv4.y;
            Ks[(c4 + 2) * ALD2 + row] = kv4.z;
            Ks[(c4 + 3) * ALD2 + row] = kv4.w;
            float4 vv4 = *(const float4*)(vb2 + row * HD + c4);
            *(float4*)&Vs[row * 64 + c4] = vv4;
        }
        __syncthreads();

        float s[16];
#pragma unroll
        for (int i = 0; i < 16; i++) s[i] = 0.f;
#pragma unroll
        for (int j = 0; j < 64; j++) {
            float4 a4 = *(float4*)&Qs[j * ALD2 + ty * 4];
            float4 b4 = *(float4*)&Ks[j * ALD2 + tx * 4];
            float a[4] = {a4.x, a4.y, a4.z, a4.w};
            float b[4] = {b4.x, b4.y, b4.z, b4.w};
#pragma unroll
            for (int i = 0; i < 4; i++)
#pragma unroll
                for (int jj = 0; jj < 4; jj++) s[i * 4 + jj] += a[i] * b[jj];
        }

        if (kt2 == qt) {
#pragma unroll
            for (int i = 0; i < 4; i++)
#pragma unroll
                for (int jj = 0; jj < 4; jj++)
                    if (tx * 4 + jj > ty * 4 + i) s[i * 4 + jj] = -1e30f;
        }

#pragma unroll
        for (int i = 0; i < 4; i++) {
            float tm = s[i * 4];
            tm = fmaxf(tm, s[i * 4 + 1]);
            tm = fmaxf(tm, s[i * 4 + 2]);
            tm = fmaxf(tm, s[i * 4 + 3]);
#pragma unroll
            for (int off = 8; off >= 1; off >>= 1)
                tm = fmaxf(tm, __shfl_xor_sync(0xffffffffu, tm, off));
            float mn = fmaxf(mrow[i], tm);
            float alpha = __expf(mrow[i] - mn);
            mrow[i] = mn;
            float rs = 0.f;
#pragma unroll
            for (int jj = 0; jj < 4; jj++) {
                float p = __expf(s[i * 4 + jj] - mn);
                s[i * 4 + jj] = p;
                rs += p;
            }
#pragma unroll
            for (int off = 8; off >= 1; off >>= 1)
                rs += __shfl_xor_sync(0xffffffffu, rs, off);
            lrow[i] = lrow[i] * alpha + rs;
#pragma unroll
            for (int jj = 0; jj < 4; jj++) o[i * 4 + jj] *= alpha;
#pragma unroll
            for (int jj = 0; jj < 4; jj++)
                Ps[(tx * 4 + jj) * ALD2 + ty * 4 + i] = s[i * 4 + jj];
        }
        __syncthreads();

#pragma unroll
        for (int j = 0; j < 64; j++) {
            float4 a4 = *(float4*)&Ps[j * ALD2 + ty * 4];
            float4 b4 = *(float4*)&Vs[j * 64 + tx * 4];
            float a[4] = {a4.x, a4.y, a4.z, a4.w};
            float b[4] = {b4.x, b4.y, b4.z, b4.w};
#pragma unroll
            for (int i = 0; i < 4; i++)
#pragma unroll
                for (int jj = 0; jj < 4; jj++) o[i * 4 + jj] += a[i] * b[jj];
        }
    }

    const int b = bh >> 4, h = bh & 15;
#pragma unroll
    for (int i = 0; i < 4; i++) {
        float inv = 1.f / lrow[i];
        int trow = qt * 64 + ty * 4 + i;
        float4 ov;
        ov.x = o[i * 4 + 0] * inv;
        ov.y = o[i * 4 + 1] * inv;
        ov.z = o[i * 4 + 2] * inv;
        ov.w = o[i * 4 + 3] * inv;
        *(float4*)(g_att + ((size_t)b * TLEN + trow) * CDIM + h * 64 + tx * 4) = ov;
    }
}

// ---------------------------------------------------------------------------
extern "C" void kernel_launch(void* const* d_in, const int* in_sizes, int n_in,
                              void* d_out, int out_size) {
    const float* x = (const float*)d_in[0];
    const float* w_qkv = (const float*)d_in[1];
    const float* w_out = (const float*)d_in[2];
    const float* b_out = (const float*)d_in[3];
    float* out = (float*)d_out;

    // 1) QKV projection (mma bf16x3, in-kernel split) -> fp32 q/k/v
    mm_kernel<<<dim3(N_QKV / 128, MTOT / 128), 256>>>(
        x, w_qkv, nullptr, nullptr, 0);

    // 2) Flash attention (proven fp32 SIMT) -> g_att (device symbol, device-side)
    size_t shm = (size_t)(3 * 64 * ALD2 + 64 * 64) * sizeof(float);
    cudaFuncSetAttribute(attn_kernel, cudaFuncAttributeMaxDynamicSharedMemorySize,
                         (int)shm);
    attn_kernel<<<dim3(TLEN / 64, BSZ * NH), 256, shm>>>();

    // 3) Output projection + bias (mma bf16x3; A = g_att resolved in-kernel)
    mm_kernel<<<dim3(CDIM / 128, MTOT / 128), 256>>>(
        nullptr, w_out, b_out, out, 1);
}

// round 8
// speedup vs baseline: 2.9359x; 1.9446x over previous
#include <cuda_runtime.h>
#include <cuda_bf16.h>
#include <cstdint>

// Problem constants
#define BSZ 4
#define TLEN 2048
#define CDIM 1024
#define NH 16
#define HD 64
#define MTOT (BSZ * TLEN)        // 8192
#define N_QKV (3 * CDIM)         // 3072
#define KDIM 1024
#define ATT_SCALE 0.125f

// ---------------------------------------------------------------------------
// Scratch (__device__ globals; referenced ONLY inside device code)
// ---------------------------------------------------------------------------
__device__ float g_q[(size_t)BSZ * NH * TLEN * HD];
__device__ float g_k[(size_t)BSZ * NH * TLEN * HD];
__device__ float g_v[(size_t)BSZ * NH * TLEN * HD];
__device__ float g_att[(size_t)MTOT * CDIM];

// ---------------------------------------------------------------------------
// Helpers (arch-agnostic PTX: mma.sync / ldmatrix only)
// ---------------------------------------------------------------------------
__device__ __forceinline__ uint32_t smem_u32(const void* p) {
    uint32_t a;
    asm("{ .reg .u64 t; cvta.to.shared.u64 t, %1; cvt.u32.u64 %0, t; }"
        : "=r"(a) : "l"(p));
    return a;
}

__device__ __forceinline__ void mma16816(float c[4], uint32_t a0, uint32_t a1,
                                         uint32_t a2, uint32_t a3,
                                         uint32_t b0, uint32_t b1) {
    asm volatile(
        "mma.sync.aligned.m16n8k16.row.col.f32.bf16.bf16.f32 "
        "{%0,%1,%2,%3}, {%4,%5,%6,%7}, {%8,%9}, {%0,%1,%2,%3};"
        : "+f"(c[0]), "+f"(c[1]), "+f"(c[2]), "+f"(c[3])
        : "r"(a0), "r"(a1), "r"(a2), "r"(a3), "r"(b0), "r"(b1));
}

__device__ __forceinline__ void ldm_x4(uint32_t r[4], uint32_t addr) {
    asm volatile("ldmatrix.sync.aligned.m8n8.x4.shared.b16 {%0,%1,%2,%3}, [%4];"
                 : "=r"(r[0]), "=r"(r[1]), "=r"(r[2]), "=r"(r[3]) : "r"(addr));
}
__device__ __forceinline__ void ldm_x4_t(uint32_t r[4], uint32_t addr) {
    asm volatile("ldmatrix.sync.aligned.m8n8.x4.trans.shared.b16 {%0,%1,%2,%3}, [%4];"
                 : "=r"(r[0]), "=r"(r[1]), "=r"(r[2]), "=r"(r[3]) : "r"(addr));
}

// pack two floats -> bf16x2, RN (used for LO parts only)
__device__ __forceinline__ uint32_t cvt2bf(float lo_val, float hi_val) {
    uint32_t r;
    asm("cvt.rn.bf16x2.f32 %0, %1, %2;" : "=r"(r) : "f"(hi_val), "f"(lo_val));
    return r;
}
// pack two floats -> bf16x2 by TRUNCATION (consistent with residual computation)
__device__ __forceinline__ uint32_t trunc2bf(float a, float b) {
    return __byte_perm(__float_as_uint(a), __float_as_uint(b), 0x7632);
}
// residual vs TRUNCATED hi
__device__ __forceinline__ float bf16res(float v) {
    return v - __uint_as_float(__float_as_uint(v) & 0xFFFF0000u);
}

// split a float4 into hi (mantissa-truncated, exact) and lo (RN of residual)
__device__ __forceinline__ void split4(float4 v, uint2& hv, uint2& lv) {
    uint32_t bx = __float_as_uint(v.x), by = __float_as_uint(v.y);
    uint32_t bz = __float_as_uint(v.z), bw = __float_as_uint(v.w);
    hv.x = __byte_perm(bx, by, 0x7632);
    hv.y = __byte_perm(bz, bw, 0x7632);
    float lx = v.x - __uint_as_float(bx & 0xFFFF0000u);
    float ly = v.y - __uint_as_float(by & 0xFFFF0000u);
    float lz = v.z - __uint_as_float(bz & 0xFFFF0000u);
    float lw = v.w - __uint_as_float(bw & 0xFFFF0000u);
    lv.x = cvt2bf(lx, ly);
    lv.y = cvt2bf(lz, lw);
}

// ---------------------------------------------------------------------------
// mma.sync bf16x3 GEMM with in-kernel fp32->hi/lo split (PROVEN R6).
// ---------------------------------------------------------------------------
#define GBK 32
#define ALDS 40
#define TILE_ELE (128 * ALDS)

__global__ __launch_bounds__(256) void mm_kernel(
    const float* __restrict__ A_arg, const float* __restrict__ B,
    const float* __restrict__ bias, float* __restrict__ out, int epi) {
    __shared__ __align__(16) uint16_t smbuf[4 * TILE_ELE];
    const int tid = threadIdx.x;
    const int lane = tid & 31, w = tid >> 5;
    const int wm = w & 3, wn = w >> 2;
    const int bm = blockIdx.y, bn = blockIdx.x;

    const float* A = (epi == 0) ? A_arg : g_att;
    const float* Ag = A + (size_t)bm * 128 * KDIM;
    const float* Bg = B + (size_t)bn * 128 * KDIM;

    float c[2][8][4];
#pragma unroll
    for (int i = 0; i < 2; i++)
#pragma unroll
        for (int j = 0; j < 8; j++)
#pragma unroll
            for (int k = 0; k < 4; k++) c[i][j][k] = 0.f;

    const uint32_t smb = smem_u32(smbuf);
    const uint32_t sAh = smb;
    const uint32_t sAl = smb + 2 * TILE_ELE;
    const uint32_t sBh = smb + 2 * (2 * TILE_ELE);
    const uint32_t sBl = smb + 2 * (3 * TILE_ELE);

    const int NIT = KDIM / GBK;
    for (int it = 0; it < NIT; it++) {
        const int kt = it * GBK;
#pragma unroll
        for (int j = 0; j < 8; j++) {
            int q = tid + j * 256;
            int tb = q >> 10;
            int r = (q >> 3) & 127;
            int c4 = (q & 7) * 4;
            const float* src = (tb ? Bg : Ag) + (size_t)r * KDIM + kt + c4;
            float4 v = *(const float4*)src;
            uint2 hv, lv;
            split4(v, hv, lv);
            uint32_t off = 2 * (r * ALDS + c4);
            *(uint2*)((char*)smbuf + ((tb ? sBh : sAh) + off - smb)) = hv;
            *(uint2*)((char*)smbuf + ((tb ? sBl : sAl) + off - smb)) = lv;
        }
        __syncthreads();

#pragma unroll
        for (int ks = 0; ks < 2; ks++) {
            uint32_t ah[2][4], al[2][4];
#pragma unroll
            for (int mi = 0; mi < 2; mi++) {
                uint32_t off = 2 * ((wm * 32 + 16 * mi + (lane & 15)) * ALDS +
                                    ks * 16 + (lane >> 4) * 8);
                ldm_x4(ah[mi], sAh + off);
                ldm_x4(al[mi], sAl + off);
            }
#pragma unroll
            for (int njp = 0; njp < 4; njp++) {
                int rowB = wn * 64 + njp * 16 + (lane & 7) + ((lane >> 4) & 1) * 8;
                uint32_t off = 2 * (rowB * ALDS + ks * 16 + ((lane >> 3) & 1) * 8);
                uint32_t bh4[4], bl4[4];
                ldm_x4(bh4, sBh + off);
                ldm_x4(bl4, sBl + off);
#pragma unroll
                for (int mi = 0; mi < 2; mi++) {
                    mma16816(c[mi][2 * njp], ah[mi][0], ah[mi][1], ah[mi][2], ah[mi][3], bh4[0], bh4[1]);
                    mma16816(c[mi][2 * njp], ah[mi][0], ah[mi][1], ah[mi][2], ah[mi][3], bl4[0], bl4[1]);
                    mma16816(c[mi][2 * njp], al[mi][0], al[mi][1], al[mi][2], al[mi][3], bh4[0], bh4[1]);
                    mma16816(c[mi][2 * njp + 1], ah[mi][0], ah[mi][1], ah[mi][2], ah[mi][3], bh4[2], bh4[3]);
                    mma16816(c[mi][2 * njp + 1], ah[mi][0], ah[mi][1], ah[mi][2], ah[mi][3], bl4[2], bl4[3]);
                    mma16816(c[mi][2 * njp + 1], al[mi][0], al[mi][1], al[mi][2], al[mi][3], bh4[2], bh4[3]);
                }
            }
        }
        __syncthreads();
    }

    const int rin = lane >> 2, col2 = (lane & 3) * 2;
#pragma unroll
    for (int mi = 0; mi < 2; mi++) {
#pragma unroll
        for (int h2 = 0; h2 < 2; h2++) {
            int m = bm * 128 + wm * 32 + mi * 16 + rin + h2 * 8;
#pragma unroll
            for (int nj = 0; nj < 8; nj++) {
                int n = bn * 128 + wn * 64 + nj * 8 + col2;
                float v0 = c[mi][nj][h2 * 2 + 0];
                float v1 = c[mi][nj][h2 * 2 + 1];
                if (epi == 0) {
                    int which = n >> 10;
                    int o = n & 1023;
                    int h = o >> 6, d = o & 63;
                    float* dst = (which == 0) ? g_q : (which == 1) ? g_k : g_v;
                    int bb = m >> 11, t = m & (TLEN - 1);
                    float2 o2; o2.x = v0; o2.y = v1;
                    *(float2*)(dst + ((size_t)(bb * NH + h) * TLEN + t) * HD + d) = o2;
                } else {
                    float2 o2;
                    o2.x = v0 + bias[n];
                    o2.y = v1 + bias[n + 1];
                    *(float2*)(out + (size_t)m * CDIM + n) = o2;
                }
            }
        }
    }
}

// ---------------------------------------------------------------------------
// FA2 attention (causal) on mma.sync bf16x3.
// CTA: 128 q-rows x one (b,h). 8 warps x 16 q-rows; kv tile 64.
// ---------------------------------------------------------------------------
#define ASTR 72
#define QH_OFF 0
#define QL_OFF (128 * ASTR)
#define KH_OFF (2 * 128 * ASTR)
#define KL_OFF (KH_OFF + 64 * ASTR)
#define VH_OFF (KL_OFF + 64 * ASTR)
#define VL_OFF (VH_OFF + 64 * ASTR)
#define AT_SMEM ((VL_OFF + 64 * ASTR) * 2)   // 73728 bytes

__global__ __launch_bounds__(256) void attn_kernel() {
    extern __shared__ __align__(16) uint16_t asmbuf[];
    const int tid = threadIdx.x;
    const int lane = tid & 31, w = tid >> 5;
    const int qt = blockIdx.x;           // 0..15
    const int bh = blockIdx.y;           // 0..63
    const uint32_t smb = smem_u32(asmbuf);

    // Load Q tile [128 x 64] fp32, scale (exact pow2), split hi/lo into smem
    {
        const float* qb = g_q + ((size_t)bh * TLEN + qt * 128) * HD;
#pragma unroll
        for (int j = 0; j < 8; j++) {
            int q = tid + j * 256;
            int r = q >> 4;
            int c4 = (q & 15) * 4;
            float4 v = *(const float4*)(qb + (size_t)r * HD + c4);
            v.x *= ATT_SCALE; v.y *= ATT_SCALE; v.z *= ATT_SCALE; v.w *= ATT_SCALE;
            uint2 hv, lv;
            split4(v, hv, lv);
            *(uint2*)(asmbuf + QH_OFF + r * ASTR + c4) = hv;
            *(uint2*)(asmbuf + QL_OFF + r * ASTR + c4) = lv;
        }
    }

    float co[8][4];
    float mrow[2] = {-1e30f, -1e30f};
    float lsum[2] = {0.f, 0.f};
#pragma unroll
    for (int j = 0; j < 8; j++)
#pragma unroll
        for (int k = 0; k < 4; k++) co[j][k] = 0.f;

    const int rin = lane >> 2, col2 = (lane & 3) * 2;
    const int kv_tiles = 2 * qt + 2;

    for (int kt = 0; kt < kv_tiles; kt++) {
        __syncthreads();
        // Load K/V tiles [64 x 64] fp32, split hi/lo
        {
            const size_t kvb = ((size_t)bh * TLEN + kt * 64) * HD;
#pragma unroll
            for (int j = 0; j < 8; j++) {
                int q = tid + j * 256;
                int tile = q >> 10;          // 0:K 1:V
                int r = (q >> 4) & 63;
                int c4 = (q & 15) * 4;
                const float* src = (tile == 0 ? g_k : g_v) + kvb + (size_t)r * HD + c4;
                float4 v = *(const float4*)src;
                uint2 hv, lv;
                split4(v, hv, lv);
                int ho = (tile == 0 ? KH_OFF : VH_OFF) + r * ASTR + c4;
                int lo = (tile == 0 ? KL_OFF : VL_OFF) + r * ASTR + c4;
                *(uint2*)(asmbuf + ho) = hv;
                *(uint2*)(asmbuf + lo) = lv;
            }
        }
        __syncthreads();

        // S = Q K^T (bf16x3)
        float cs[8][4];
#pragma unroll
        for (int j = 0; j < 8; j++)
#pragma unroll
            for (int k = 0; k < 4; k++) cs[j][k] = 0.f;

#pragma unroll
        for (int ks = 0; ks < 4; ks++) {
            uint32_t aoff = 2 * ((16 * w + (lane & 15)) * ASTR + ks * 16 + (lane >> 4) * 8);
            uint32_t aq_h[4], aq_l[4];
            ldm_x4(aq_h, smb + 2 * QH_OFF + aoff);
            ldm_x4(aq_l, smb + 2 * QL_OFF + aoff);
#pragma unroll
            for (int njp = 0; njp < 4; njp++) {
                int rowK = njp * 16 + (lane & 7) + ((lane >> 4) & 1) * 8;
                uint32_t boff = 2 * (rowK * ASTR + ks * 16 + ((lane >> 3) & 1) * 8);
                uint32_t bh4[4], bl4[4];
                ldm_x4(bh4, smb + 2 * KH_OFF + boff);
                ldm_x4(bl4, smb + 2 * KL_OFF + boff);
                mma16816(cs[2 * njp], aq_h[0], aq_h[1], aq_h[2], aq_h[3], bh4[0], bh4[1]);
                mma16816(cs[2 * njp], aq_h[0], aq_h[1], aq_h[2], aq_h[3], bl4[0], bl4[1]);
                mma16816(cs[2 * njp], aq_l[0], aq_l[1], aq_l[2], aq_l[3], bh4[0], bh4[1]);
                mma16816(cs[2 * njp + 1], aq_h[0], aq_h[1], aq_h[2], aq_h[3], bh4[2], bh4[3]);
                mma16816(cs[2 * njp + 1], aq_h[0], aq_h[1], aq_h[2], aq_h[3], bl4[2], bl4[3]);
                mma16816(cs[2 * njp + 1], aq_l[0], aq_l[1], aq_l[2], aq_l[3], bh4[2], bh4[3]);
            }
        }

        // Causal mask
        if (kt >= 2 * qt) {
#pragma unroll
            for (int nj = 0; nj < 8; nj++)
#pragma unroll
                for (int h2 = 0; h2 < 2; h2++) {
                    int qr = qt * 128 + 16 * w + rin + 8 * h2;
                    int kc = kt * 64 + nj * 8 + col2;
                    if (kc > qr) cs[nj][2 * h2] = -1e30f;
                    if (kc + 1 > qr) cs[nj][2 * h2 + 1] = -1e30f;
                }
        }

        // Online softmax (rows rin, rin+8; reduce over quad lanes)
#pragma unroll
        for (int h2 = 0; h2 < 2; h2++) {
            float mx = -1e30f;
#pragma unroll
            for (int nj = 0; nj < 8; nj++) {
                mx = fmaxf(mx, cs[nj][2 * h2]);
                mx = fmaxf(mx, cs[nj][2 * h2 + 1]);
            }
            mx = fmaxf(mx, __shfl_xor_sync(0xffffffffu, mx, 1));
            mx = fmaxf(mx, __shfl_xor_sync(0xffffffffu, mx, 2));
            float mn = fmaxf(mrow[h2], mx);
            float alpha = __expf(mrow[h2] - mn);
            mrow[h2] = mn;
            float rs = 0.f;
#pragma unroll
            for (int nj = 0; nj < 8; nj++) {
                float p0 = __expf(cs[nj][2 * h2] - mn);
                float p1 = __expf(cs[nj][2 * h2 + 1] - mn);
                cs[nj][2 * h2] = p0;
                cs[nj][2 * h2 + 1] = p1;
                rs += p0 + p1;
            }
            rs += __shfl_xor_sync(0xffffffffu, rs, 1);
            rs += __shfl_xor_sync(0xffffffffu, rs, 2);
            lsum[h2] = lsum[h2] * alpha + rs;
#pragma unroll
            for (int nj = 0; nj < 8; nj++) {
                co[nj][2 * h2] *= alpha;
                co[nj][2 * h2 + 1] *= alpha;
            }
        }

        // O += P V (bf16x3); P A-frags: hi = TRUNCATION, lo = RN(residual)
        // (consistency of hi/lo convention is load-bearing: RN-hi with
        //  trunc-residual-lo leaves 2^-9 uncompensated -> rel_err 3e-3)
#pragma unroll
        for (int kk = 0; kk < 4; kk++) {
            uint32_t ph[4], pl[4];
            ph[0] = trunc2bf(cs[2 * kk][0], cs[2 * kk][1]);
            ph[1] = trunc2bf(cs[2 * kk][2], cs[2 * kk][3]);
            ph[2] = trunc2bf(cs[2 * kk + 1][0], cs[2 * kk + 1][1]);
            ph[3] = trunc2bf(cs[2 * kk + 1][2], cs[2 * kk + 1][3]);
            pl[0] = cvt2bf(bf16res(cs[2 * kk][0]), bf16res(cs[2 * kk][1]));
            pl[1] = cvt2bf(bf16res(cs[2 * kk][2]), bf16res(cs[2 * kk][3]));
            pl[2] = cvt2bf(bf16res(cs[2 * kk + 1][0]), bf16res(cs[2 * kk + 1][1]));
            pl[3] = cvt2bf(bf16res(cs[2 * kk + 1][2]), bf16res(cs[2 * kk + 1][3]));
#pragma unroll
            for (int djp = 0; djp < 4; djp++) {
                int rowV = kk * 16 + (lane & 7) + ((lane >> 3) & 1) * 8;
                uint32_t voff = 2 * (rowV * ASTR + djp * 16 + (lane >> 4) * 8);
                uint32_t bv_h[4], bv_l[4];
                ldm_x4_t(bv_h, smb + 2 * VH_OFF + voff);
                ldm_x4_t(bv_l, smb + 2 * VL_OFF + voff);
                mma16816(co[2 * djp], ph[0], ph[1], ph[2], ph[3], bv_h[0], bv_h[1]);
                mma16816(co[2 * djp], ph[0], ph[1], ph[2], ph[3], bv_l[0], bv_l[1]);
                mma16816(co[2 * djp], pl[0], pl[1], pl[2], pl[3], bv_h[0], bv_h[1]);
                mma16816(co[2 * djp + 1], ph[0], ph[1], ph[2], ph[3], bv_h[2], bv_h[3]);
                mma16816(co[2 * djp + 1], ph[0], ph[1], ph[2], ph[3], bv_l[2], bv_l[3]);
                mma16816(co[2 * djp + 1], pl[0], pl[1], pl[2], pl[3], bv_h[2], bv_h[3]);
            }
        }
    }

    // Epilogue: normalize, write fp32 to g_att [b, t, h*64 + d]
    const int b = bh >> 4, h = bh & 15;
#pragma unroll
    for (int h2 = 0; h2 < 2; h2++) {
        float inv = 1.f / lsum[h2];
        int t = qt * 128 + 16 * w + rin + 8 * h2;
        size_t base = ((size_t)b * TLEN + t) * CDIM + h * 64;
#pragma unroll
        for (int nj = 0; nj < 8; nj++) {
            int d = nj * 8 + col2;
            float2 o2;
            o2.x = co[nj][2 * h2] * inv;
            o2.y = co[nj][2 * h2 + 1] * inv;
            *(float2*)(g_att + base + d) = o2;
        }
    }
}

// ---------------------------------------------------------------------------
extern "C" void kernel_launch(void* const* d_in, const int* in_sizes, int n_in,
                              void* d_out, int out_size) {
    const float* x = (const float*)d_in[0];
    const float* w_qkv = (const float*)d_in[1];
    const float* w_out = (const float*)d_in[2];
    const float* b_out = (const float*)d_in[3];
    float* out = (float*)d_out;

    cudaFuncSetAttribute(attn_kernel, cudaFuncAttributeMaxDynamicSharedMemorySize,
                         AT_SMEM);

    // 1) QKV projection (mma bf16x3) -> fp32 q/k/v
    mm_kernel<<<dim3(N_QKV / 128, MTOT / 128), 256>>>(
        x, w_qkv, nullptr, nullptr, 0);

    // 2) FA2 attention (mma bf16x3) -> g_att
    attn_kernel<<<dim3(TLEN / 128, BSZ * NH), 256, AT_SMEM>>>();

    // 3) Output projection + bias (mma bf16x3; A = g_att resolved in-kernel)
    mm_kernel<<<dim3(CDIM / 128, MTOT / 128), 256>>>(
        nullptr, w_out, b_out, out, 1);
}